// round 6
// baseline (speedup 1.0000x reference)
#include <cuda_runtime.h>

#define HID 128
#define VOCAB 28
#define N_NODES_MAX 100000
#define N_EDGES_MAX 1600000

// ---- device scratch (no allocations allowed) ----
// Packed per-node histogram: 8 uint32 per node = 28 byte-counters + pad = one 32B sector.
__device__ __align__(16) unsigned g_cntp[N_NODES_MAX * 8];   // 3.2 MB
__device__ float g_Ep[VOCAB * HID];     // embed @ (w1_0 @ w2_0)
__device__ float g_b0c[HID];            // b1_0 @ w2_0 + b2_0
__device__ float g_Wc[HID];             // w1_1 @ w2_1
__device__ float g_scal[3];             // {1+eps0, 1+eps1, b1_1.w2_1 + b2_1}
__device__ float g_z1[N_NODES_MAX];     // relu(h0) . Wc  per node
__device__ float g_xfall[N_NODES_MAX];  // fallback x buffer if output has no x region

// ---- one init kernel: folded weights + scalars + zero hist + zero y ----
__global__ void __launch_bounds__(128)
k_init(const float* __restrict__ embed, const float* __restrict__ w1_0,
       const float* __restrict__ b1_0,  const float* __restrict__ w2_0,
       const float* __restrict__ b2_0,  const float* __restrict__ w1_1,
       const float* __restrict__ b1_1,  const float* __restrict__ w2_1,
       const float* __restrict__ b2_1,  const float* __restrict__ eps0,
       const float* __restrict__ eps1,
       float* __restrict__ y_out, int y_len, int n_nodes) {
    int b = blockIdx.x, j = threadIdx.x;
    if (b < VOCAB) {
        __shared__ float sT[HID];
        float acc = 0.f;
        #pragma unroll 8
        for (int m = 0; m < HID; m++) acc = fmaf(embed[b * HID + m], w1_0[m * HID + j], acc);
        sT[j] = acc;
        __syncthreads();
        float acc2 = 0.f;
        #pragma unroll 8
        for (int k = 0; k < HID; k++) acc2 = fmaf(sT[k], w2_0[k * HID + j], acc2);
        g_Ep[b * HID + j] = acc2;
    } else if (b == VOCAB) {            // b0c = b1_0 @ w2_0 + b2_0
        float acc = b2_0[j];
        #pragma unroll 8
        for (int k = 0; k < HID; k++) acc = fmaf(b1_0[k], w2_0[k * HID + j], acc);
        g_b0c[j] = acc;
    } else if (b == VOCAB + 1) {        // Wc = w1_1 @ w2_1
        float acc = 0.f;
        #pragma unroll 8
        for (int jj = 0; jj < HID; jj++) acc = fmaf(w1_1[j * HID + jj], w2_1[jj], acc);
        g_Wc[j] = acc;
    } else if (b == VOCAB + 2) {        // scalars + zero y_out
        if (j == 0) {
            float bc = b2_1[0];
            for (int jj = 0; jj < HID; jj++) bc = fmaf(b1_1[jj], w2_1[jj], bc);
            g_scal[0] = 1.f + eps0[0];
            g_scal[1] = 1.f + eps1[0];
            g_scal[2] = bc;
        }
        for (int i = j; i < y_len; i += 128) y_out[i] = 0.f;
    } else {                            // zero g_cntp (uint4 stores)
        uint4* p = (uint4*)g_cntp;
        int nq = n_nodes * 2;
        int idx = (b - (VOCAB + 3)) * 128 + j;
        int stride = (gridDim.x - (VOCAB + 3)) * 128;
        uint4 z = make_uint4(0u, 0u, 0u, 0u);
        for (int i = idx; i < nq; i += stride) p[i] = z;
    }
}

// ---- edge histogram: 16 edges/thread, front-batched loads for MLP ----
__global__ void __launch_bounds__(256)
k_hist(const int* __restrict__ src, const int* __restrict__ dst,
       const int* __restrict__ xidx, int n4, int n_edges) {
    const int tidg = blockIdx.x * blockDim.x + threadIdx.x;
    const int stride = gridDim.x * blockDim.x;
    int4 s[4], d[4];
    bool ok[4];
    #pragma unroll
    for (int u = 0; u < 4; u++) {
        int i = tidg + u * stride;
        ok[u] = (i < n4);
        if (ok[u]) { s[u] = ((const int4*)src)[i]; d[u] = ((const int4*)dst)[i]; }
    }
    int t[16];
    #pragma unroll
    for (int u = 0; u < 4; u++) {
        if (ok[u]) {
            t[u*4+0] = xidx[s[u].x]; t[u*4+1] = xidx[s[u].y];
            t[u*4+2] = xidx[s[u].z]; t[u*4+3] = xidx[s[u].w];
        }
    }
    #pragma unroll
    for (int u = 0; u < 4; u++) {
        if (ok[u]) {
            atomicAdd(&g_cntp[d[u].x * 8 + (t[u*4+0] >> 2)], 1u << ((t[u*4+0] & 3) * 8));
            atomicAdd(&g_cntp[d[u].y * 8 + (t[u*4+1] >> 2)], 1u << ((t[u*4+1] & 3) * 8));
            atomicAdd(&g_cntp[d[u].z * 8 + (t[u*4+2] >> 2)], 1u << ((t[u*4+2] & 3) * 8));
            atomicAdd(&g_cntp[d[u].w * 8 + (t[u*4+3] >> 2)], 1u << ((t[u*4+3] & 3) * 8));
        }
    }
    // remainder edges (n_edges not multiple of 4)
    int e = n4 * 4 + tidg;
    if (e < n_edges) {
        int tt = xidx[src[e]];
        atomicAdd(&g_cntp[dst[e] * 8 + (tt >> 2)], 1u << ((tt & 3) * 8));
    }
}

// ---- fused layer0 + z1 + x_out init: one warp per node, grid-stride ----
__global__ void __launch_bounds__(256)
k_node(const int* __restrict__ xidx, float* __restrict__ x_out, int n_nodes) {
    __shared__ __align__(16) float sEp[VOCAB * HID];
    __shared__ __align__(16) float sB[HID];
    __shared__ __align__(16) float sW[HID];
    int tid = threadIdx.x;
    for (int i = tid; i < VOCAB * HID; i += 256) sEp[i] = g_Ep[i];
    if (tid < HID) { sB[tid] = g_b0c[tid]; sW[tid] = g_Wc[tid]; }
    __syncthreads();

    float eps0p = g_scal[0], eps1p = g_scal[1], bc = g_scal[2];
    int lane = tid & 31;
    int j0 = lane * 4;
    float4 w4 = *(const float4*)&sW[j0];
    float4 b4 = *(const float4*)&sB[j0];
    int wglob = blockIdx.x * 8 + (tid >> 5);
    int wstride = gridDim.x * 8;

    for (int node = wglob; node < n_nodes; node += wstride) {
        unsigned w = 0;
        if (lane < 8) w = g_cntp[node * 8 + lane];   // one sector per node
        int tn = xidx[node];
        float4 acc = b4;
        {
            float4 e4 = *(const float4*)&sEp[tn * HID + j0];
            acc.x = fmaf(eps0p, e4.x, acc.x); acc.y = fmaf(eps0p, e4.y, acc.y);
            acc.z = fmaf(eps0p, e4.z, acc.z); acc.w = fmaf(eps0p, e4.w, acc.w);
        }
        #pragma unroll
        for (int t = 0; t < VOCAB; t++) {
            unsigned wt = __shfl_sync(0xffffffffu, w, t >> 2);
            unsigned ct = (wt >> ((t & 3) * 8)) & 255u;
            if (ct) {
                float f = (float)ct;
                float4 e4 = *(const float4*)&sEp[t * HID + j0];
                acc.x = fmaf(f, e4.x, acc.x); acc.y = fmaf(f, e4.y, acc.y);
                acc.z = fmaf(f, e4.z, acc.z); acc.w = fmaf(f, e4.w, acc.w);
            }
        }
        float s = fmaxf(acc.x, 0.f) * w4.x + fmaxf(acc.y, 0.f) * w4.y
                + fmaxf(acc.z, 0.f) * w4.z + fmaxf(acc.w, 0.f) * w4.w;
        #pragma unroll
        for (int o = 16; o > 0; o >>= 1) s += __shfl_xor_sync(0xffffffffu, s, o);
        if (lane == 0) {
            g_z1[node] = s;
            x_out[node] = fmaf(eps1p, s, bc);
        }
    }
}

// ---- layer1 scalar scatter into x_out: 16 edges/thread, front-batched ----
__global__ void __launch_bounds__(256)
k_scatter(const int* __restrict__ src, const int* __restrict__ dst,
          float* __restrict__ x_out, int n4, int n_edges) {
    const int tidg = blockIdx.x * blockDim.x + threadIdx.x;
    const int stride = gridDim.x * blockDim.x;
    int4 s[4], d[4];
    bool ok[4];
    #pragma unroll
    for (int u = 0; u < 4; u++) {
        int i = tidg + u * stride;
        ok[u] = (i < n4);
        if (ok[u]) { s[u] = ((const int4*)src)[i]; d[u] = ((const int4*)dst)[i]; }
    }
    float z[16];
    #pragma unroll
    for (int u = 0; u < 4; u++) {
        if (ok[u]) {
            z[u*4+0] = g_z1[s[u].x]; z[u*4+1] = g_z1[s[u].y];
            z[u*4+2] = g_z1[s[u].z]; z[u*4+3] = g_z1[s[u].w];
        }
    }
    #pragma unroll
    for (int u = 0; u < 4; u++) {
        if (ok[u]) {
            atomicAdd(&x_out[d[u].x], z[u*4+0]);
            atomicAdd(&x_out[d[u].y], z[u*4+1]);
            atomicAdd(&x_out[d[u].z], z[u*4+2]);
            atomicAdd(&x_out[d[u].w], z[u*4+3]);
        }
    }
    int e = n4 * 4 + tidg;
    if (e < n_edges) atomicAdd(&x_out[dst[e]], g_z1[src[e]]);
}

// ---- graph readout: sorted batch -> warp-segmented reduce ----
__global__ void __launch_bounds__(256)
k_final(const int* __restrict__ batch, const float* __restrict__ x_out,
        float* __restrict__ y_out, int n_nodes) {
    int n = blockIdx.x * blockDim.x + threadIdx.x;
    float v = 0.f;
    int g = -1;
    if (n < n_nodes) { v = x_out[n]; g = batch[n]; }
    int lane = threadIdx.x & 31;
    #pragma unroll
    for (int d = 1; d < 32; d <<= 1) {
        float up = __shfl_up_sync(0xffffffffu, v, d);
        int gu = __shfl_up_sync(0xffffffffu, g, d);
        if (lane >= d && gu == g) v += up;
    }
    int gd = __shfl_down_sync(0xffffffffu, g, 1);
    bool last = (lane == 31) || (gd != g);
    if (n < n_nodes && last) atomicAdd(&y_out[g], v);
}

extern "C" void kernel_launch(void* const* d_in, const int* in_sizes, int n_in,
                              void* d_out, int out_size) {
    const int*   x_idx    = (const int*)d_in[0];
    const int*   edge_src = (const int*)d_in[1];
    const int*   edge_dst = (const int*)d_in[2];
    const int*   batch    = (const int*)d_in[3];
    const float* embed    = (const float*)d_in[4];
    const float* eps0     = (const float*)d_in[5];
    const float* w1_0     = (const float*)d_in[6];
    const float* b1_0     = (const float*)d_in[7];
    const float* w2_0     = (const float*)d_in[8];
    const float* b2_0     = (const float*)d_in[9];
    const float* eps1     = (const float*)d_in[10];
    const float* w1_1     = (const float*)d_in[11];
    const float* b1_1     = (const float*)d_in[12];
    const float* w2_1     = (const float*)d_in[13];
    const float* b2_1     = (const float*)d_in[14];

    int n_nodes = in_sizes[0];
    int n_edges = in_sizes[1];
    if (n_nodes > N_NODES_MAX) n_nodes = N_NODES_MAX;
    if (n_edges > N_EDGES_MAX) n_edges = N_EDGES_MAX;

    float* out = (float*)d_out;
    float* y_out;
    float* x_out;
    int y_len;
    if (out_size >= n_nodes + 1) {     // (y_hat, x) concatenated, y first
        y_len = out_size - n_nodes;
        y_out = out;
        x_out = out + y_len;
    } else {
        y_len = out_size;
        y_out = out;
        x_out = g_xfall;
    }

    int n4 = n_edges >> 2;
    // 16 edges per thread -> threads cover n4/4 int4 groups
    int nthreads = (n4 + 3) / 4;
    int eblocks = (nthreads + 255) / 256;

    k_init<<<VOCAB + 3 + 1536, 128>>>(embed, w1_0, b1_0, w2_0, b2_0,
                                      w1_1, b1_1, w2_1, b2_1, eps0, eps1,
                                      y_out, y_len, n_nodes);
    k_hist<<<eblocks, 256>>>(edge_src, edge_dst, x_idx, n4, n_edges);
    k_node<<<592, 256>>>(x_idx, x_out, n_nodes);
    k_scatter<<<eblocks, 256>>>(edge_src, edge_dst, x_out, n4, n_edges);
    k_final<<<(n_nodes + 255) / 256, 256>>>(batch, x_out, y_out, n_nodes);
}

// round 7
// speedup vs baseline: 1.0894x; 1.0894x over previous
#include <cuda_runtime.h>

#define HID 128
#define VOCAB 28
#define N_NODES_MAX 100000
#define N_EDGES_MAX 1600000
#define FOLD_BLOCKS 31   // 28 Ep rows + b0c + Wc + scalars

// ---- device scratch (no allocations allowed) ----
// Packed per-node histogram: 8 uint32 per node = 28 byte-counters + pad = one 32B sector.
__device__ __align__(16) unsigned g_cntp[N_NODES_MAX * 8];   // 3.2 MB
__device__ float g_Ep[VOCAB * HID];     // embed @ (w1_0 @ w2_0)
__device__ float g_b0c[HID];            // b1_0 @ w2_0 + b2_0
__device__ float g_Wc[HID];             // w1_1 @ w2_1
__device__ float g_scal[3];             // {1+eps0, 1+eps1, b1_1.w2_1 + b2_1}
__device__ float g_z1[N_NODES_MAX];     // relu(h0) . Wc  per node
__device__ float g_xfall[N_NODES_MAX];  // fallback x buffer if output lacks x region

// ---- zero hist scratch + y region (fast uint4 memset) ----
__global__ void __launch_bounds__(256)
k_zero(float* __restrict__ y_out, int y_len, int n_nodes) {
    int i = blockIdx.x * blockDim.x + threadIdx.x;
    int stride = gridDim.x * blockDim.x;
    uint4* p = (uint4*)g_cntp;
    int nq = n_nodes * 2;                       // 8 words = 2 uint4 per node
    uint4 z = make_uint4(0u, 0u, 0u, 0u);
    for (int idx = i; idx < nq; idx += stride) p[idx] = z;
    for (int idx = i; idx < y_len; idx += stride) y_out[idx] = 0.f;
}

// ---- fused: weight folding (blocks 0..30) + edge histogram (blocks 31..) ----
__global__ void __launch_bounds__(256)
k_hist_fold(const int* __restrict__ src, const int* __restrict__ dst,
            const int* __restrict__ xidx, int n4, int n_edges,
            const float* __restrict__ embed, const float* __restrict__ w1_0,
            const float* __restrict__ b1_0,  const float* __restrict__ w2_0,
            const float* __restrict__ b2_0,  const float* __restrict__ w1_1,
            const float* __restrict__ b1_1,  const float* __restrict__ w2_1,
            const float* __restrict__ b2_1,  const float* __restrict__ eps0,
            const float* __restrict__ eps1) {
    int b = blockIdx.x;
    if (b < FOLD_BLOCKS) {
        int j = threadIdx.x;
        if (j >= HID) return;
        if (b < VOCAB) {
            // Ep[b][:] = (embed[b] @ w1_0) @ w2_0  — staged via smem, 4-acc full unroll
            __shared__ float sT[HID];
            float a0 = 0.f, a1 = 0.f, a2 = 0.f, a3 = 0.f;
            #pragma unroll
            for (int m = 0; m < HID; m += 4) {
                a0 = fmaf(embed[b * HID + m + 0], w1_0[(m + 0) * HID + j], a0);
                a1 = fmaf(embed[b * HID + m + 1], w1_0[(m + 1) * HID + j], a1);
                a2 = fmaf(embed[b * HID + m + 2], w1_0[(m + 2) * HID + j], a2);
                a3 = fmaf(embed[b * HID + m + 3], w1_0[(m + 3) * HID + j], a3);
            }
            sT[j] = (a0 + a1) + (a2 + a3);
            __syncthreads();
            float c0 = 0.f, c1 = 0.f, c2 = 0.f, c3 = 0.f;
            #pragma unroll
            for (int k = 0; k < HID; k += 4) {
                c0 = fmaf(sT[k + 0], w2_0[(k + 0) * HID + j], c0);
                c1 = fmaf(sT[k + 1], w2_0[(k + 1) * HID + j], c1);
                c2 = fmaf(sT[k + 2], w2_0[(k + 2) * HID + j], c2);
                c3 = fmaf(sT[k + 3], w2_0[(k + 3) * HID + j], c3);
            }
            g_Ep[b * HID + j] = (c0 + c1) + (c2 + c3);
        } else if (b == VOCAB) {        // b0c = b1_0 @ w2_0 + b2_0
            float c0 = b2_0[j], c1 = 0.f, c2 = 0.f, c3 = 0.f;
            #pragma unroll
            for (int k = 0; k < HID; k += 4) {
                c0 = fmaf(b1_0[k + 0], w2_0[(k + 0) * HID + j], c0);
                c1 = fmaf(b1_0[k + 1], w2_0[(k + 1) * HID + j], c1);
                c2 = fmaf(b1_0[k + 2], w2_0[(k + 2) * HID + j], c2);
                c3 = fmaf(b1_0[k + 3], w2_0[(k + 3) * HID + j], c3);
            }
            g_b0c[j] = (c0 + c1) + (c2 + c3);
        } else if (b == VOCAB + 1) {    // Wc = w1_1 @ w2_1
            float c0 = 0.f, c1 = 0.f, c2 = 0.f, c3 = 0.f;
            #pragma unroll
            for (int k = 0; k < HID; k += 4) {
                c0 = fmaf(w1_1[j * HID + k + 0], w2_1[k + 0], c0);
                c1 = fmaf(w1_1[j * HID + k + 1], w2_1[k + 1], c1);
                c2 = fmaf(w1_1[j * HID + k + 2], w2_1[k + 2], c2);
                c3 = fmaf(w1_1[j * HID + k + 3], w2_1[k + 3], c3);
            }
            g_Wc[j] = (c0 + c1) + (c2 + c3);
        } else if (j == 0) {            // scalars
            float bc = b2_1[0];
            for (int jj = 0; jj < HID; jj++) bc = fmaf(b1_1[jj], w2_1[jj], bc);
            g_scal[0] = 1.f + eps0[0];
            g_scal[1] = 1.f + eps1[0];
            g_scal[2] = bc;
        }
        return;
    }
    // ---- histogram part: 4 edges per thread (proven-best R5 shape) ----
    int i = (b - FOLD_BLOCKS) * blockDim.x + threadIdx.x;
    if (i < n4) {
        int4 s = ((const int4*)src)[i];
        int4 d = ((const int4*)dst)[i];
        int t0 = xidx[s.x], t1 = xidx[s.y], t2 = xidx[s.z], t3 = xidx[s.w];
        atomicAdd(&g_cntp[d.x * 8 + (t0 >> 2)], 1u << ((t0 & 3) * 8));
        atomicAdd(&g_cntp[d.y * 8 + (t1 >> 2)], 1u << ((t1 & 3) * 8));
        atomicAdd(&g_cntp[d.z * 8 + (t2 >> 2)], 1u << ((t2 & 3) * 8));
        atomicAdd(&g_cntp[d.w * 8 + (t3 >> 2)], 1u << ((t3 & 3) * 8));
    }
    int e = n4 * 4 + i;
    if (e < n_edges) {
        int t = xidx[src[e]];
        atomicAdd(&g_cntp[dst[e] * 8 + (t >> 2)], 1u << ((t & 3) * 8));
    }
}

// ---- fused layer0 + z1 + x_out init: one warp per node, grid-stride ----
__global__ void __launch_bounds__(256)
k_node(const int* __restrict__ xidx, float* __restrict__ x_out, int n_nodes) {
    __shared__ __align__(16) float sEp[VOCAB * HID];
    __shared__ __align__(16) float sB[HID];
    __shared__ __align__(16) float sW[HID];
    int tid = threadIdx.x;
    for (int i = tid; i < VOCAB * HID; i += 256) sEp[i] = g_Ep[i];
    if (tid < HID) { sB[tid] = g_b0c[tid]; sW[tid] = g_Wc[tid]; }
    __syncthreads();

    float eps0p = g_scal[0], eps1p = g_scal[1], bc = g_scal[2];
    int lane = tid & 31;
    int j0 = lane * 4;
    float4 w4 = *(const float4*)&sW[j0];
    float4 b4 = *(const float4*)&sB[j0];
    int wglob = blockIdx.x * 8 + (tid >> 5);
    int wstride = gridDim.x * 8;

    for (int node = wglob; node < n_nodes; node += wstride) {
        unsigned w = 0;
        if (lane < 8) w = g_cntp[node * 8 + lane];   // one sector per node
        int tn = xidx[node];
        float4 acc = b4;
        {
            float4 e4 = *(const float4*)&sEp[tn * HID + j0];
            acc.x = fmaf(eps0p, e4.x, acc.x); acc.y = fmaf(eps0p, e4.y, acc.y);
            acc.z = fmaf(eps0p, e4.z, acc.z); acc.w = fmaf(eps0p, e4.w, acc.w);
        }
        #pragma unroll
        for (int t = 0; t < VOCAB; t++) {
            unsigned wt = __shfl_sync(0xffffffffu, w, t >> 2);
            unsigned ct = (wt >> ((t & 3) * 8)) & 255u;
            if (ct) {                                 // warp-uniform: no divergence
                float f = (float)ct;
                float4 e4 = *(const float4*)&sEp[t * HID + j0];
                acc.x = fmaf(f, e4.x, acc.x); acc.y = fmaf(f, e4.y, acc.y);
                acc.z = fmaf(f, e4.z, acc.z); acc.w = fmaf(f, e4.w, acc.w);
            }
        }
        float s = fmaxf(acc.x, 0.f) * w4.x + fmaxf(acc.y, 0.f) * w4.y
                + fmaxf(acc.z, 0.f) * w4.z + fmaxf(acc.w, 0.f) * w4.w;
        #pragma unroll
        for (int o = 16; o > 0; o >>= 1) s += __shfl_xor_sync(0xffffffffu, s, o);
        if (lane == 0) {
            g_z1[node] = s;
            x_out[node] = fmaf(eps1p, s, bc);   // (1+eps1)*z1 + bias; scatter adds on top
        }
    }
}

// ---- layer1 scalar scatter into x_out: 4 edges/thread (R5 shape) ----
__global__ void __launch_bounds__(256)
k_scatter(const int* __restrict__ src, const int* __restrict__ dst,
          float* __restrict__ x_out, int n4, int n_edges) {
    int i = blockIdx.x * blockDim.x + threadIdx.x;
    if (i < n4) {
        int4 s = ((const int4*)src)[i];
        int4 d = ((const int4*)dst)[i];
        float z0 = g_z1[s.x], z1v = g_z1[s.y], z2 = g_z1[s.z], z3 = g_z1[s.w];
        atomicAdd(&x_out[d.x], z0);
        atomicAdd(&x_out[d.y], z1v);
        atomicAdd(&x_out[d.z], z2);
        atomicAdd(&x_out[d.w], z3);
    }
    int e = n4 * 4 + i;
    if (e < n_edges) atomicAdd(&x_out[dst[e]], g_z1[src[e]]);
}

// ---- graph readout: sorted batch -> warp-segmented reduce ----
__global__ void __launch_bounds__(256)
k_final(const int* __restrict__ batch, const float* __restrict__ x_out,
        float* __restrict__ y_out, int n_nodes) {
    int n = blockIdx.x * blockDim.x + threadIdx.x;
    float v = 0.f;
    int g = -1;
    if (n < n_nodes) { v = x_out[n]; g = batch[n]; }
    int lane = threadIdx.x & 31;
    #pragma unroll
    for (int d = 1; d < 32; d <<= 1) {
        float up = __shfl_up_sync(0xffffffffu, v, d);
        int gu = __shfl_up_sync(0xffffffffu, g, d);
        if (lane >= d && gu == g) v += up;
    }
    int gd = __shfl_down_sync(0xffffffffu, g, 1);
    bool last = (lane == 31) || (gd != g);
    if (n < n_nodes && last) atomicAdd(&y_out[g], v);
}

extern "C" void kernel_launch(void* const* d_in, const int* in_sizes, int n_in,
                              void* d_out, int out_size) {
    const int*   x_idx    = (const int*)d_in[0];
    const int*   edge_src = (const int*)d_in[1];
    const int*   edge_dst = (const int*)d_in[2];
    const int*   batch    = (const int*)d_in[3];
    const float* embed    = (const float*)d_in[4];
    const float* eps0     = (const float*)d_in[5];
    const float* w1_0     = (const float*)d_in[6];
    const float* b1_0     = (const float*)d_in[7];
    const float* w2_0     = (const float*)d_in[8];
    const float* b2_0     = (const float*)d_in[9];
    const float* eps1     = (const float*)d_in[10];
    const float* w1_1     = (const float*)d_in[11];
    const float* b1_1     = (const float*)d_in[12];
    const float* w2_1     = (const float*)d_in[13];
    const float* b2_1     = (const float*)d_in[14];

    int n_nodes = in_sizes[0];
    int n_edges = in_sizes[1];
    if (n_nodes > N_NODES_MAX) n_nodes = N_NODES_MAX;
    if (n_edges > N_EDGES_MAX) n_edges = N_EDGES_MAX;

    float* out = (float*)d_out;
    float* y_out;
    float* x_out;
    int y_len;
    if (out_size >= n_nodes + 1) {     // (y_hat, x) concatenated, y first
        y_len = out_size - n_nodes;
        y_out = out;
        x_out = out + y_len;
    } else {
        y_len = out_size;
        y_out = out;
        x_out = g_xfall;
    }

    int n4 = n_edges >> 2;
    int eblocks = (n4 + 255) / 256;    // one int4 group (4 edges) per thread

    k_zero<<<512, 256>>>(y_out, y_len, n_nodes);
    k_hist_fold<<<FOLD_BLOCKS + eblocks, 256>>>(
        edge_src, edge_dst, x_idx, n4, n_edges,
        embed, w1_0, b1_0, w2_0, b2_0, w1_1, b1_1, w2_1, b2_1, eps0, eps1);
    k_node<<<592, 256>>>(x_idx, x_out, n_nodes);
    k_scatter<<<eblocks, 256>>>(edge_src, edge_dst, x_out, n4, n_edges);
    k_final<<<(n_nodes + 255) / 256, 256>>>(batch, x_out, y_out, n_nodes);
}